// round 15
// baseline (speedup 1.0000x reference)
#include <cuda_runtime.h>
#include <cuda_bf16.h>

// ---------------- problem dims (fixed) ----------------
#define QLEN 1024
#define BSZ 4
#define DM 1024
#define NH 16
#define DH 64
#define T_TOK 4096
#define NZ 64

// ---------------- scratch (device globals; no cudaMalloc allowed) ----------------
__device__ float g_QW[(size_t)NZ * QLEN * DH];
__device__ float g_QR[(size_t)NZ * QLEN * DH];
__device__ float g_Kb[(size_t)NZ * QLEN * DH];
__device__ float g_Vb[(size_t)NZ * QLEN * DH];
__device__ float g_RK[(size_t)NZ * QLEN * DH];
__device__ float g_BD[(size_t)NZ * QLEN * QLEN + 2048];
__device__ float g_AV[(size_t)T_TOK * DM];
__device__ float g_AO[(size_t)T_TOK * DM];
// tf32 pre-rounded operand copies
__device__ float g_wt  [(size_t)T_TOK * DM];
__device__ float g_rt  [(size_t)T_TOK * DM];
__device__ float g_qkvwt[(size_t)3 * DM * DM];
__device__ float g_rnetwt[(size_t)DM * DM];
__device__ float g_owt [(size_t)DM * DM];

__device__ __forceinline__ unsigned f2tf32(float x) {
    unsigned r;
    asm("cvt.rna.tf32.f32 %0, %1;" : "=r"(r) : "f"(x));
    return r;
}
__device__ __forceinline__ float ex2f(float x) {
    float y;
    asm("ex2.approx.f32 %0, %1;" : "=f"(y) : "f"(x));
    return y;
}

#define MMA_TF32(d0,d1,d2,d3, a0,a1,a2,a3, b0,b1) \
    asm volatile( \
        "mma.sync.aligned.m16n8k8.row.col.f32.tf32.tf32.f32 " \
        "{%0,%1,%2,%3}, {%4,%5,%6,%7}, {%8,%9}, {%0,%1,%2,%3};" \
        : "+f"(d0), "+f"(d1), "+f"(d2), "+f"(d3) \
        : "r"(a0), "r"(a1), "r"(a2), "r"(a3), "r"(b0), "r"(b1))

#define LDSM4(r0,r1,r2,r3, addr) \
    asm volatile("ldmatrix.sync.aligned.m8n8.x4.shared.b16 {%0,%1,%2,%3}, [%4];" \
        : "=r"(r0), "=r"(r1), "=r"(r2), "=r"(r3) : "r"(addr))

#define CP16(dst_u32, src_ptr) \
    asm volatile("cp.async.cg.shared.global [%0], [%1], 16;" \
                 :: "r"(dst_u32), "l"(src_ptr))
#define CP4(dst_u32, src_ptr) \
    asm volatile("cp.async.ca.shared.global [%0], [%1], 4;" \
                 :: "r"(dst_u32), "l"(src_ptr))
#define CP_COMMIT() asm volatile("cp.async.commit_group;")
#define CP_WAIT(n)  asm volatile("cp.async.wait_group %0;" :: "n"(n))

// ---------------- merged RNA tf32 round of all 5 operand arrays ----------------
// segments (in float4 units): w 1Mi | r 1Mi | qkv_w 768Ki | r_net_w 256Ki | o_w 256Ki
__global__ void __launch_bounds__(256) round_all_kernel(
    const float* __restrict__ w, const float* __restrict__ r,
    const float* __restrict__ qkvw, const float* __restrict__ rnetw,
    const float* __restrict__ ow)
{
    int i = blockIdx.x * 256 + threadIdx.x;   // 0 .. 3.25Mi-1
    const float* src; float* dst; int off;
    float *wt, *rt, *qt, *nt, *ot;
    // device globals referenced directly
    wt = g_wt; rt = g_rt; qt = g_qkvwt; nt = g_rnetwt; ot = g_owt;
    if (i < 1048576)        { src = w;     dst = wt; off = i; }
    else if (i < 2097152)   { src = r;     dst = rt; off = i - 1048576; }
    else if (i < 2883584)   { src = qkvw;  dst = qt; off = i - 2097152; }
    else if (i < 3145728)   { src = rnetw; dst = nt; off = i - 2883584; }
    else                    { src = ow;    dst = ot; off = i - 3145728; }
    float4 v = *(const float4*)(src + (size_t)off * 4);
    uint4 u = make_uint4(f2tf32(v.x), f2tf32(v.y), f2tf32(v.z), f2tf32(v.w));
    *(uint4*)(dst + (size_t)off * 4) = u;
}

// ---------------- mma.sync tf32 GEMM, 3-stage cp.async pipeline ----------------
// C[M,N] = A[M,K] @ B[N,K]^T. Inputs MUST be pre-rounded to tf32 (RNA).
// 128x128 tile, BK=32, 8 warps (4M x 2N).
// mode 0: plain row-major store to C (tri=2 skips bx+by<gridDim.x-1).
// mode 1: QKV scatter epilogue -> g_QW/g_QR (q + biases), g_Kb, g_Vb.
// mode 2: R scatter epilogue -> g_RK.
#define SSTRIDE 36
#define STAGE_B 36864
#define GEMM_SMEM (3 * STAGE_B)

__global__ void __launch_bounds__(256) gemm_mma_kernel(
    const float* __restrict__ A, const float* __restrict__ B, float* __restrict__ C,
    int M, int N, int K, long long sA, long long sB, long long sC, int tri,
    int mode, const float* __restrict__ rwb, const float* __restrict__ rrb)
{
    int bx = blockIdx.x, by = blockIdx.y, z = blockIdx.z;
    if (tri == 2 && (bx + by) < (int)gridDim.x - 1) return;

    extern __shared__ float smp[];
    unsigned sbase = (unsigned)__cvta_generic_to_shared(smp);

    int tid = threadIdx.x;
    int wid = tid >> 5, lane = tid & 31;
    int warp_m = wid & 3, warp_n = wid >> 2;
    int r = lane >> 2, cc = lane & 3;
    int lrow = lane & 7, lsel = lane >> 3;

    unsigned a_base[2], b_base[4];
#pragma unroll
    for (int mi = 0; mi < 2; mi++)
        a_base[mi] = (unsigned)(((warp_m * 32 + mi * 16 + (lsel & 1) * 8 + lrow) * SSTRIDE
                                 + (lsel >> 1) * 4) * 4);
#pragma unroll
    for (int p = 0; p < 4; p++)
        b_base[p] = (unsigned)(((warp_n * 64 + p * 16 + (lsel >> 1) * 8 + lrow) * SSTRIDE
                                + (lsel & 1) * 4) * 4) + 18432u;

    const float* Ab = A + (long long)z * sA + (long long)(by * 128) * K;
    const float* Bb = B + (long long)z * sB + (long long)(bx * 128) * K;

    float acc[2][8][4];
#pragma unroll
    for (int mi = 0; mi < 2; mi++)
#pragma unroll
        for (int ni = 0; ni < 8; ni++)
#pragma unroll
            for (int q = 0; q < 4; q++) acc[mi][ni][q] = 0.f;

    int nch = K >> 5;

    for (int s0 = 0; s0 < 2 && s0 < nch; s0++) {
        unsigned st = sbase + (unsigned)(s0 * STAGE_B);
        int k0 = s0 << 5;
#pragma unroll
        for (int s = tid; s < 1024; s += 256) {
            int row = s >> 3, q = s & 7;
            unsigned off = (unsigned)(row * SSTRIDE + q * 4) * 4u;
            CP16(st + off, Ab + (long long)row * K + k0 + q * 4);
            CP16(st + 18432u + off, Bb + (long long)row * K + k0 + q * 4);
        }
        CP_COMMIT();
    }

    for (int c = 0; c < nch; c++) {
        if (c + 1 < nch) { CP_WAIT(1); } else { CP_WAIT(0); }
        __syncthreads();

        if (c + 2 < nch) {
            int k0 = (c + 2) << 5;
            unsigned st = sbase + (unsigned)(((c + 2) % 3) * STAGE_B);
#pragma unroll
            for (int s = tid; s < 1024; s += 256) {
                int row = s >> 3, q = s & 7;
                unsigned off = (unsigned)(row * SSTRIDE + q * 4) * 4u;
                CP16(st + off, Ab + (long long)row * K + k0 + q * 4);
                CP16(st + 18432u + off, Bb + (long long)row * K + k0 + q * 4);
            }
            CP_COMMIT();
        }

        unsigned stg = sbase + (unsigned)((c % 3) * STAGE_B);
#pragma unroll
        for (int ks = 0; ks < 4; ks++) {
            unsigned kbB = (unsigned)ks * 32u;
            unsigned a[2][4], bq[4][4];
            LDSM4(a[0][0], a[0][1], a[0][2], a[0][3], stg + a_base[0] + kbB);
            LDSM4(a[1][0], a[1][1], a[1][2], a[1][3], stg + a_base[1] + kbB);
#pragma unroll
            for (int p = 0; p < 4; p++)
                LDSM4(bq[p][0], bq[p][1], bq[p][2], bq[p][3], stg + b_base[p] + kbB);
#pragma unroll
            for (int ni = 0; ni < 8; ni++) {
                unsigned b0 = bq[ni >> 1][(ni & 1) * 2];
                unsigned b1 = bq[ni >> 1][(ni & 1) * 2 + 1];
#pragma unroll
                for (int mi = 0; mi < 2; mi++) {
                    MMA_TF32(acc[mi][ni][0], acc[mi][ni][1], acc[mi][ni][2], acc[mi][ni][3],
                             a[mi][0], a[mi][1], a[mi][2], a[mi][3], b0, b1);
                }
            }
        }
    }

    if (mode == 0) {
        float* Cb = C + (long long)z * sC;
#pragma unroll
        for (int mi = 0; mi < 2; mi++) {
            int m = by * 128 + warp_m * 32 + mi * 16 + r;
#pragma unroll
            for (int ni = 0; ni < 8; ni++) {
                int n = bx * 128 + warp_n * 64 + ni * 8 + cc * 2;
                *(float2*)(Cb + (long long)m * N + n) =
                    make_float2(acc[mi][ni][0], acc[mi][ni][1]);
                *(float2*)(Cb + (long long)(m + 8) * N + n) =
                    make_float2(acc[mi][ni][2], acc[mi][ni][3]);
            }
        }
    } else if (mode == 1) {
        // QKV scatter: tile column block entirely inside one part (1024 | 8*128)
        int part = bx >> 3;                 // 0=q, 1=k, 2=v
#pragma unroll
        for (int mi = 0; mi < 2; mi++) {
#pragma unroll
            for (int half = 0; half < 2; half++) {
                int m = by * 128 + warp_m * 32 + mi * 16 + r + half * 8;
                int i = m >> 2, bb2 = m & 3;
#pragma unroll
                for (int ni = 0; ni < 8; ni++) {
                    int hd = (bx & 7) * 128 + warp_n * 64 + ni * 8 + cc * 2;
                    int h = hd >> 6, d = hd & 63;
                    size_t idx = (((size_t)(bb2 * 16 + h) * QLEN + i) * DH + d);
                    float v0 = acc[mi][ni][half * 2];
                    float v1 = acc[mi][ni][half * 2 + 1];
                    if (part == 0) {
                        *(uint2*)(g_QW + idx) =
                            make_uint2(f2tf32(v0 + rwb[hd]), f2tf32(v1 + rwb[hd + 1]));
                        *(uint2*)(g_QR + idx) =
                            make_uint2(f2tf32(v0 + rrb[hd]), f2tf32(v1 + rrb[hd + 1]));
                    } else if (part == 1) {
                        *(uint2*)(g_Kb + idx) = make_uint2(f2tf32(v0), f2tf32(v1));
                    } else {
                        *(uint2*)(g_Vb + idx) = make_uint2(f2tf32(v0), f2tf32(v1));
                    }
                }
            }
        }
    } else {
        // R scatter -> g_RK
#pragma unroll
        for (int mi = 0; mi < 2; mi++) {
#pragma unroll
            for (int half = 0; half < 2; half++) {
                int m = by * 128 + warp_m * 32 + mi * 16 + r + half * 8;
                int i = m >> 2, bb2 = m & 3;
#pragma unroll
                for (int ni = 0; ni < 8; ni++) {
                    int hd = bx * 128 + warp_n * 64 + ni * 8 + cc * 2;
                    int h = hd >> 6, d = hd & 63;
                    size_t idx = (((size_t)(bb2 * 16 + h) * QLEN + i) * DH + d);
                    *(uint2*)(g_RK + idx) =
                        make_uint2(f2tf32(acc[mi][ni][half * 2]),
                                   f2tf32(acc[mi][ni][half * 2 + 1]));
                }
            }
        }
    }
}

// ---------------- semi-fused attention ----------------
#define QK_STR 68
#define VP_STR 132
#define A_KS  0
#define A_VS  8704
#define A_PS  17152
#define ATTN_SMEM ((17152 + 16896) * 4)

__global__ void __launch_bounds__(256) attn_kernel(
    const float* __restrict__ BD, const float* __restrict__ Kb,
    const float* __restrict__ Vb, const float* __restrict__ QW,
    float* __restrict__ AV)
{
    extern __shared__ float sm[];
    unsigned* Ps = (unsigned*)(sm + A_PS);
    unsigned sb = (unsigned)__cvta_generic_to_shared(sm);
    unsigned ks_a  = sb + A_KS * 4u;
    unsigned vs_a  = sb + A_VS * 4u;
    unsigned ps_a  = sb + A_PS * 4u;

    int it = (int)gridDim.x - 1 - blockIdx.x;
    int z = blockIdx.y;
    int b = z >> 4, h = z & 15;
    const float* Kz  = Kb + (long long)z * (QLEN * DH);
    const float* Vz  = Vb + (long long)z * (QLEN * DH);
    const float* QWz = QW + (long long)z * (QLEN * DH);
    const float* BDz = BD + (long long)z * (QLEN * QLEN);

    int tid = threadIdx.x;
    int wid = tid >> 5, lane = tid & 31;
    int r = lane >> 2, cc = lane & 3;
    int lrow = lane & 7, lsel = lane >> 3;
    int i0 = it << 7;
    int m0 = wid * 16;
    int rowA = m0 + r;
    int iA = i0 + rowA, iB = iA + 8;

    unsigned a_qk = (unsigned)(((m0 + (lsel & 1) * 8 + lrow) * QK_STR + (lsel >> 1) * 4) * 4);
    unsigned a_pv = ps_a + (unsigned)(((m0 + (lsel & 1) * 8 + lrow) * VP_STR + (lsel >> 1) * 4) * 4);
    unsigned bk_base[8], bv_base[4];
#pragma unroll
    for (int p = 0; p < 8; p++)
        bk_base[p] = ks_a + (unsigned)(((p * 16 + (lsel >> 1) * 8 + lrow) * QK_STR + (lsel & 1) * 4) * 4);
#pragma unroll
    for (int p = 0; p < 4; p++)
        bv_base[p] = vs_a + (unsigned)(((p * 16 + (lsel >> 1) * 8 + lrow) * VP_STR + (lsel & 1) * 4) * 4);

    float oacc[8][4];
#pragma unroll
    for (int ni = 0; ni < 8; ni++)
#pragma unroll
        for (int q = 0; q < 4; q++) oacc[ni][q] = 0.f;

    float mA = -1e30f, mB = -1e30f, lA = 0.f, lB = 0.f;

#pragma unroll
    for (int s = tid; s < 2048; s += 256) {
        int row = s >> 4, q = s & 15;
        CP16(ks_a + (unsigned)(row * QK_STR + q * 4) * 4u,
             Kz + (long long)row * DH + q * 4);
        CP16(ps_a + (unsigned)(row * QK_STR + q * 4) * 4u,
             QWz + (long long)(i0 + row) * DH + q * 4);
    }
    CP_COMMIT();
    CP_WAIT(0);
    __syncthreads();

    unsigned qwf[8][4];
#pragma unroll
    for (int ks = 0; ks < 8; ks++) {
        LDSM4(qwf[ks][0], qwf[ks][1], qwf[ks][2], qwf[ks][3],
              ps_a + a_qk + (unsigned)ks * 32u);
    }
    __syncthreads();

    const float SC2 = 0.18033688f;   // 0.125 * log2(e)

    for (int jt = 0; jt <= it; jt++) {
        int j0 = jt << 7;

#pragma unroll
        for (int s = tid; s < 8192; s += 256) {
            int d = s & 63, j = s >> 6;
            CP4(vs_a + (unsigned)(d * VP_STR + j) * 4u,
                Vz + (long long)(j0 + j) * DH + d);
        }
        CP_COMMIT();

        if (jt > 0) { CP_WAIT(1); }
        __syncthreads();

        float s_fr[16][4];
#pragma unroll
        for (int ni = 0; ni < 16; ni++)
#pragma unroll
            for (int q = 0; q < 4; q++) s_fr[ni][q] = 0.f;
#pragma unroll
        for (int ks = 0; ks < 8; ks++) {
            unsigned kbB = (unsigned)ks * 32u;
#pragma unroll
            for (int p = 0; p < 8; p++) {
                unsigned b0a, b1a, b0b, b1b;
                LDSM4(b0a, b1a, b0b, b1b, bk_base[p] + kbB);
                MMA_TF32(s_fr[2 * p][0], s_fr[2 * p][1], s_fr[2 * p][2], s_fr[2 * p][3],
                         qwf[ks][0], qwf[ks][1], qwf[ks][2], qwf[ks][3], b0a, b1a);
                MMA_TF32(s_fr[2 * p + 1][0], s_fr[2 * p + 1][1], s_fr[2 * p + 1][2], s_fr[2 * p + 1][3],
                         qwf[ks][0], qwf[ks][1], qwf[ks][2], qwf[ks][3], b0b, b1b);
            }
        }
        __syncthreads();

        if (jt < it) {
            int jn0 = (jt + 1) << 7;
#pragma unroll
            for (int s = tid; s < 2048; s += 256) {
                int row = s >> 4, q = s & 15;
                CP16(ks_a + (unsigned)(row * QK_STR + q * 4) * 4u,
                     Kz + (long long)(jn0 + row) * DH + q * 4);
            }
            CP_COMMIT();
            CP_WAIT(1);
        } else {
            CP_WAIT(0);
        }
        __syncthreads();

        {
            const float* bdA = BDz + (long long)iA * QLEN + (j0 - iA + QLEN - 1);
            const float* bdB = BDz + (long long)iB * QLEN + (j0 - iB + QLEN - 1);
            bool diag = (jt == it);
#pragma unroll
            for (int ni = 0; ni < 16; ni++) {
                int c0 = ni * 8 + cc * 2;
                float v0 = (s_fr[ni][0] + bdA[c0])     * SC2;
                float v1 = (s_fr[ni][1] + bdA[c0 + 1]) * SC2;
                float v2 = (s_fr[ni][2] + bdB[c0])     * SC2;
                float v3 = (s_fr[ni][3] + bdB[c0 + 1]) * SC2;
                if (diag) {
                    if (j0 + c0     > iA) v0 = -1e30f;
                    if (j0 + c0 + 1 > iA) v1 = -1e30f;
                    if (j0 + c0     > iB) v2 = -1e30f;
                    if (j0 + c0 + 1 > iB) v3 = -1e30f;
                }
                s_fr[ni][0] = v0; s_fr[ni][1] = v1;
                s_fr[ni][2] = v2; s_fr[ni][3] = v3;
            }
            float mxA = -1e30f, mxB = -1e30f;
#pragma unroll
            for (int ni = 0; ni < 16; ni++) {
                mxA = fmaxf(mxA, fmaxf(s_fr[ni][0], s_fr[ni][1]));
                mxB = fmaxf(mxB, fmaxf(s_fr[ni][2], s_fr[ni][3]));
            }
#pragma unroll
            for (int off = 1; off <= 2; off <<= 1) {
                mxA = fmaxf(mxA, __shfl_xor_sync(0xffffffffu, mxA, off));
                mxB = fmaxf(mxB, __shfl_xor_sync(0xffffffffu, mxB, off));
            }
            float mnA = fmaxf(mA, mxA), mnB = fmaxf(mB, mxB);
            float alA = ex2f(mA - mnA), alB = ex2f(mB - mnB);
            float psA = 0.f, psB = 0.f;
#pragma unroll
            for (int ni = 0; ni < 16; ni++) {
                float p0 = ex2f(s_fr[ni][0] - mnA);
                float p1 = ex2f(s_fr[ni][1] - mnA);
                float p2 = ex2f(s_fr[ni][2] - mnB);
                float p3 = ex2f(s_fr[ni][3] - mnB);
                psA += p0 + p1; psB += p2 + p3;
                int c0 = ni * 8 + cc * 2;
                *(uint2*)(Ps + rowA * VP_STR + c0) = make_uint2(f2tf32(p0), f2tf32(p1));
                *(uint2*)(Ps + (rowA + 8) * VP_STR + c0) = make_uint2(f2tf32(p2), f2tf32(p3));
            }
#pragma unroll
            for (int off = 1; off <= 2; off <<= 1) {
                psA += __shfl_xor_sync(0xffffffffu, psA, off);
                psB += __shfl_xor_sync(0xffffffffu, psB, off);
            }
            mA = mnA; mB = mnB;
            lA = lA * alA + psA; lB = lB * alB + psB;
#pragma unroll
            for (int ni = 0; ni < 8; ni++) {
                oacc[ni][0] *= alA; oacc[ni][1] *= alA;
                oacc[ni][2] *= alB; oacc[ni][3] *= alB;
            }
        }
        __syncwarp();

#pragma unroll
        for (int ks = 0; ks < 16; ks++) {
            unsigned kbB = (unsigned)ks * 32u;
            unsigned a0, a1, a2, a3;
            LDSM4(a0, a1, a2, a3, a_pv + kbB);
#pragma unroll
            for (int p = 0; p < 4; p++) {
                unsigned b0a, b1a, b0b, b1b;
                LDSM4(b0a, b1a, b0b, b1b, bv_base[p] + kbB);
                MMA_TF32(oacc[2 * p][0], oacc[2 * p][1], oacc[2 * p][2], oacc[2 * p][3],
                         a0, a1, a2, a3, b0a, b1a);
                MMA_TF32(oacc[2 * p + 1][0], oacc[2 * p + 1][1], oacc[2 * p + 1][2], oacc[2 * p + 1][3],
                         a0, a1, a2, a3, b0b, b1b);
            }
        }
        __syncthreads();
    }

    float invA = 1.f / lA, invB = 1.f / lB;
    long long ta = (long long)iA * BSZ + b;
    long long tb = (long long)iB * BSZ + b;
#pragma unroll
    for (int ni = 0; ni < 8; ni++) {
        int d = ni * 8 + cc * 2;
        *(uint2*)(AV + ta * DM + h * 64 + d) =
            make_uint2(f2tf32(oacc[ni][0] * invA), f2tf32(oacc[ni][1] * invA));
        *(uint2*)(AV + tb * DM + h * 64 + d) =
            make_uint2(f2tf32(oacc[ni][2] * invB), f2tf32(oacc[ni][3] * invB));
    }
}

// ---------------- residual + layernorm ----------------
__global__ void __launch_bounds__(256) ln_kernel(
    const float* __restrict__ w, const float* __restrict__ ao,
    const float* __restrict__ g, const float* __restrict__ be,
    float* __restrict__ out)
{
    long long t = blockIdx.x;
    int tid = threadIdx.x;
    __shared__ float red[8];
    __shared__ float s_mu, s_rstd;

    float4 wx = *(const float4*)(w  + t * DM + tid * 4);
    float4 ax = *(const float4*)(ao + t * DM + tid * 4);
    float x0 = wx.x + ax.x, x1 = wx.y + ax.y, x2 = wx.z + ax.z, x3 = wx.w + ax.w;

    float s = x0 + x1 + x2 + x3;
#pragma unroll
    for (int off = 16; off >= 1; off >>= 1) s += __shfl_xor_sync(0xffffffffu, s, off);
    if ((tid & 31) == 0) red[tid >> 5] = s;
    __syncthreads();
    if (tid == 0) {
        float a = 0;
#pragma unroll
        for (int i2 = 0; i2 < 8; i2++) a += red[i2];
        s_mu = a * (1.f / DM);
    }
    __syncthreads();
    float mu = s_mu;
    float d0 = x0 - mu, d1 = x1 - mu, d2 = x2 - mu, d3 = x3 - mu;
    float v = d0 * d0 + d1 * d1 + d2 * d2 + d3 * d3;
#pragma unroll
    for (int off = 16; off >= 1; off >>= 1) v += __shfl_xor_sync(0xffffffffu, v, off);
    if ((tid & 31) == 0) red[tid >> 5] = v;
    __syncthreads();
    if (tid == 0) {
        float a = 0;
#pragma unroll
        for (int i2 = 0; i2 < 8; i2++) a += red[i2];
        s_rstd = rsqrtf(a * (1.f / DM) + 1e-5f);
    }
    __syncthreads();
    float rs = s_rstd;
    float4 gg = *(const float4*)(g  + tid * 4);
    float4 bb = *(const float4*)(be + tid * 4);
    float4 o = make_float4(d0 * rs * gg.x + bb.x, d1 * rs * gg.y + bb.y,
                           d2 * rs * gg.z + bb.z, d3 * rs * gg.w + bb.w);
    *(float4*)(out + t * DM + tid * 4) = o;
}

// ---------------- host launcher ----------------
extern "C" void kernel_launch(void* const* d_in, const int* in_sizes, int n_in,
                              void* d_out, int out_size)
{
    const float* w       = (const float*)d_in[0];
    const float* r       = (const float*)d_in[1];
    const float* rwb     = (const float*)d_in[2];
    const float* rrb     = (const float*)d_in[3];
    const float* qkv_w   = (const float*)d_in[4];
    const float* r_net_w = (const float*)d_in[5];
    const float* o_w     = (const float*)d_in[6];
    const float* gamma   = (const float*)d_in[7];
    const float* beta    = (const float*)d_in[8];
    float* out = (float*)d_out;

    float *QW, *Kb, *Vb, *RK, *QR, *BD, *AV, *AO;
    float *wt, *rt, *qkvwt, *rnetwt, *owt;
    cudaGetSymbolAddress((void**)&QW, g_QW);
    cudaGetSymbolAddress((void**)&QR, g_QR);
    cudaGetSymbolAddress((void**)&Kb, g_Kb);
    cudaGetSymbolAddress((void**)&Vb, g_Vb);
    cudaGetSymbolAddress((void**)&RK, g_RK);
    cudaGetSymbolAddress((void**)&BD, g_BD);
    cudaGetSymbolAddress((void**)&AV, g_AV);
    cudaGetSymbolAddress((void**)&AO, g_AO);
    cudaGetSymbolAddress((void**)&wt, g_wt);
    cudaGetSymbolAddress((void**)&rt, g_rt);
    cudaGetSymbolAddress((void**)&qkvwt, g_qkvwt);
    cudaGetSymbolAddress((void**)&rnetwt, g_rnetwt);
    cudaGetSymbolAddress((void**)&owt, g_owt);

    cudaFuncSetAttribute(gemm_mma_kernel, cudaFuncAttributeMaxDynamicSharedMemorySize, GEMM_SMEM);
    cudaFuncSetAttribute(attn_kernel, cudaFuncAttributeMaxDynamicSharedMemorySize, ATTN_SMEM);

    // 0) pre-round all operands to tf32 (one merged launch; 3.25Mi float4s)
    round_all_kernel<<<(3407872 + 255) / 256, 256>>>(w, r, qkv_w, r_net_w, o_w);

    // 1) QKV GEMM with scatter epilogue -> QW/QR/Kb/Vb (split fused)
    gemm_mma_kernel<<<dim3(3072 / 128, T_TOK / 128, 1), 256, GEMM_SMEM>>>(
        wt, qkvwt, AO, T_TOK, 3072, DM, 0, 0, 0, 0, 1, rwb, rrb);
    // 2) R GEMM with scatter epilogue -> RK
    gemm_mma_kernel<<<dim3(DM / 128, T_TOK / 128, 1), 256, GEMM_SMEM>>>(
        rt, rnetwt, AO, T_TOK, DM, DM, 0, 0, 0, 0, 2, rwb, rrb);
    // 3) BD = QR . RK   batched, band tiles
    gemm_mma_kernel<<<dim3(QLEN / 128, QLEN / 128, NZ), 256, GEMM_SMEM>>>(
        QR, RK, BD, QLEN, QLEN, DH,
        (long long)QLEN * DH, (long long)QLEN * DH, (long long)QLEN * QLEN, 2, 0, rwb, rrb);
    // 4) semi-fused attention (writes AV pre-rounded)
    attn_kernel<<<dim3(QLEN / 128, NZ), 256, ATTN_SMEM>>>(BD, Kb, Vb, QW, AV);
    // 5) attn_out = AV @ owt^T
    gemm_mma_kernel<<<dim3(DM / 128, T_TOK / 128, 1), 256, GEMM_SMEM>>>(
        AV, owt, AO, T_TOK, DM, DM, 0, 0, 0, 0, 0, rwb, rrb);
    // 6) residual + layernorm -> out (uses raw w)
    ln_kernel<<<T_TOK, 256>>>(w, AO, gamma, beta, out);
}

// round 16
// speedup vs baseline: 1.1076x; 1.1076x over previous
#include <cuda_runtime.h>
#include <cuda_bf16.h>

// ---------------- problem dims (fixed) ----------------
#define QLEN 1024
#define BSZ 4
#define DM 1024
#define NH 16
#define DH 64
#define T_TOK 4096
#define NZ 64

// ---------------- scratch (device globals; no cudaMalloc allowed) ----------------
__device__ float g_wheads[(size_t)T_TOK * 3 * DM];
__device__ float g_rkraw [(size_t)T_TOK * DM];
__device__ float g_QW[(size_t)NZ * QLEN * DH];
__device__ float g_QR[(size_t)NZ * QLEN * DH];
__device__ float g_Kb[(size_t)NZ * QLEN * DH];
__device__ float g_Vb[(size_t)NZ * QLEN * DH];
__device__ float g_RK[(size_t)NZ * QLEN * DH];
__device__ float g_BD[(size_t)NZ * QLEN * QLEN + 2048];
__device__ float g_AV[(size_t)T_TOK * DM];
__device__ float g_AO[(size_t)T_TOK * DM];
// tf32 pre-rounded operand copies
__device__ float g_wt  [(size_t)T_TOK * DM];
__device__ float g_rt  [(size_t)T_TOK * DM];
__device__ float g_qkvwt[(size_t)3 * DM * DM];
__device__ float g_rnetwt[(size_t)DM * DM];
__device__ float g_owt [(size_t)DM * DM];

__device__ __forceinline__ unsigned f2tf32(float x) {
    unsigned r;
    asm("cvt.rna.tf32.f32 %0, %1;" : "=r"(r) : "f"(x));
    return r;
}
__device__ __forceinline__ float ex2f(float x) {
    float y;
    asm("ex2.approx.f32 %0, %1;" : "=f"(y) : "f"(x));
    return y;
}

#define MMA_TF32(d0,d1,d2,d3, a0,a1,a2,a3, b0,b1) \
    asm volatile( \
        "mma.sync.aligned.m16n8k8.row.col.f32.tf32.tf32.f32 " \
        "{%0,%1,%2,%3}, {%4,%5,%6,%7}, {%8,%9}, {%0,%1,%2,%3};" \
        : "+f"(d0), "+f"(d1), "+f"(d2), "+f"(d3) \
        : "r"(a0), "r"(a1), "r"(a2), "r"(a3), "r"(b0), "r"(b1))

#define LDSM4(r0,r1,r2,r3, addr) \
    asm volatile("ldmatrix.sync.aligned.m8n8.x4.shared.b16 {%0,%1,%2,%3}, [%4];" \
        : "=r"(r0), "=r"(r1), "=r"(r2), "=r"(r3) : "r"(addr))

#define CP16(dst_u32, src_ptr) \
    asm volatile("cp.async.cg.shared.global [%0], [%1], 16;" \
                 :: "r"(dst_u32), "l"(src_ptr))
#define CP4(dst_u32, src_ptr) \
    asm volatile("cp.async.ca.shared.global [%0], [%1], 4;" \
                 :: "r"(dst_u32), "l"(src_ptr))
#define CP_COMMIT() asm volatile("cp.async.commit_group;")
#define CP_WAIT(n)  asm volatile("cp.async.wait_group %0;" :: "n"(n))

// ---------------- merged RNA tf32 round of all 5 operand arrays ----------------
// segments (in float4 units): w 1Mi | r 1Mi | qkv_w 768Ki | r_net_w 256Ki | o_w 256Ki
__global__ void __launch_bounds__(256) round_all_kernel(
    const float* __restrict__ w, const float* __restrict__ r,
    const float* __restrict__ qkvw, const float* __restrict__ rnetw,
    const float* __restrict__ ow)
{
    int i = blockIdx.x * 256 + threadIdx.x;   // 0 .. 3,407,871
    const float* src; float* dst; int off;
    if (i < 1048576)        { src = w;     dst = g_wt;     off = i; }
    else if (i < 2097152)   { src = r;     dst = g_rt;     off = i - 1048576; }
    else if (i < 2883584)   { src = qkvw;  dst = g_qkvwt;  off = i - 2097152; }
    else if (i < 3145728)   { src = rnetw; dst = g_rnetwt; off = i - 2883584; }
    else                    { src = ow;    dst = g_owt;    off = i - 3145728; }
    float4 v = *(const float4*)(src + (size_t)off * 4);
    uint4 u = make_uint4(f2tf32(v.x), f2tf32(v.y), f2tf32(v.z), f2tf32(v.w));
    *(uint4*)(dst + (size_t)off * 4) = u;
}

// ---------------- mma.sync tf32 GEMM, 3-stage cp.async pipeline ----------------
// C[M,N] = A[M,K] @ B[N,K]^T. Inputs MUST be pre-rounded to tf32 (RNA):
// hw truncation in the MMA is then exact. 128x128 tile, BK=32, 8 warps (4M x 2N).
// tri=2: skip bx+by<gridDim.x-1 (BD band).
#define SSTRIDE 36
#define STAGE_B 36864
#define GEMM_SMEM (3 * STAGE_B)

__global__ void __launch_bounds__(256, 2) gemm_mma_kernel(
    const float* __restrict__ A, const float* __restrict__ B, float* __restrict__ C,
    int M, int N, int K, long long sA, long long sB, long long sC, int tri)
{
    int bx = blockIdx.x, by = blockIdx.y, z = blockIdx.z;
    if (tri == 2 && (bx + by) < (int)gridDim.x - 1) return;

    extern __shared__ float smp[];
    unsigned sbase = (unsigned)__cvta_generic_to_shared(smp);

    int tid = threadIdx.x;
    int wid = tid >> 5, lane = tid & 31;
    int warp_m = wid & 3, warp_n = wid >> 2;
    int r = lane >> 2, cc = lane & 3;
    int lrow = lane & 7, lsel = lane >> 3;

    unsigned a_base[2], b_base[4];
#pragma unroll
    for (int mi = 0; mi < 2; mi++)
        a_base[mi] = (unsigned)(((warp_m * 32 + mi * 16 + (lsel & 1) * 8 + lrow) * SSTRIDE
                                 + (lsel >> 1) * 4) * 4);
#pragma unroll
    for (int p = 0; p < 4; p++)
        b_base[p] = (unsigned)(((warp_n * 64 + p * 16 + (lsel >> 1) * 8 + lrow) * SSTRIDE
                                + (lsel & 1) * 4) * 4) + 18432u;

    const float* Ab = A + (long long)z * sA + (long long)(by * 128) * K;
    const float* Bb = B + (long long)z * sB + (long long)(bx * 128) * K;

    float acc[2][8][4];
#pragma unroll
    for (int mi = 0; mi < 2; mi++)
#pragma unroll
        for (int ni = 0; ni < 8; ni++)
#pragma unroll
            for (int q = 0; q < 4; q++) acc[mi][ni][q] = 0.f;

    int nch = K >> 5;

    for (int s0 = 0; s0 < 2 && s0 < nch; s0++) {
        unsigned st = sbase + (unsigned)(s0 * STAGE_B);
        int k0 = s0 << 5;
#pragma unroll
        for (int s = tid; s < 1024; s += 256) {
            int row = s >> 3, q = s & 7;
            unsigned off = (unsigned)(row * SSTRIDE + q * 4) * 4u;
            CP16(st + off, Ab + (long long)row * K + k0 + q * 4);
            CP16(st + 18432u + off, Bb + (long long)row * K + k0 + q * 4);
        }
        CP_COMMIT();
    }

    for (int c = 0; c < nch; c++) {
        if (c + 1 < nch) { CP_WAIT(1); } else { CP_WAIT(0); }
        __syncthreads();

        if (c + 2 < nch) {
            int k0 = (c + 2) << 5;
            unsigned st = sbase + (unsigned)(((c + 2) % 3) * STAGE_B);
#pragma unroll
            for (int s = tid; s < 1024; s += 256) {
                int row = s >> 3, q = s & 7;
                unsigned off = (unsigned)(row * SSTRIDE + q * 4) * 4u;
                CP16(st + off, Ab + (long long)row * K + k0 + q * 4);
                CP16(st + 18432u + off, Bb + (long long)row * K + k0 + q * 4);
            }
            CP_COMMIT();
        }

        unsigned stg = sbase + (unsigned)((c % 3) * STAGE_B);
#pragma unroll
        for (int ks = 0; ks < 4; ks++) {
            unsigned kbB = (unsigned)ks * 32u;
            unsigned a[2][4], bq[4][4];
            LDSM4(a[0][0], a[0][1], a[0][2], a[0][3], stg + a_base[0] + kbB);
            LDSM4(a[1][0], a[1][1], a[1][2], a[1][3], stg + a_base[1] + kbB);
#pragma unroll
            for (int p = 0; p < 4; p++)
                LDSM4(bq[p][0], bq[p][1], bq[p][2], bq[p][3], stg + b_base[p] + kbB);
#pragma unroll
            for (int ni = 0; ni < 8; ni++) {
                unsigned b0 = bq[ni >> 1][(ni & 1) * 2];
                unsigned b1 = bq[ni >> 1][(ni & 1) * 2 + 1];
#pragma unroll
                for (int mi = 0; mi < 2; mi++) {
                    MMA_TF32(acc[mi][ni][0], acc[mi][ni][1], acc[mi][ni][2], acc[mi][ni][3],
                             a[mi][0], a[mi][1], a[mi][2], a[mi][3], b0, b1);
                }
            }
        }
    }

    float* Cb = C + (long long)z * sC;
#pragma unroll
    for (int mi = 0; mi < 2; mi++) {
        int m = by * 128 + warp_m * 32 + mi * 16 + r;
#pragma unroll
        for (int ni = 0; ni < 8; ni++) {
            int n = bx * 128 + warp_n * 64 + ni * 8 + cc * 2;
            *(float2*)(Cb + (long long)m * N + n) =
                make_float2(acc[mi][ni][0], acc[mi][ni][1]);
            *(float2*)(Cb + (long long)(m + 8) * N + n) =
                make_float2(acc[mi][ni][2], acc[mi][ni][3]);
        }
    }
}

// ---------------- split heads + biases (pre-rounded to tf32 via RNA) ----------------
__global__ void __launch_bounds__(256) split_kernel(
    const float* __restrict__ wheads, const float* __restrict__ rkraw,
    const float* __restrict__ rwb, const float* __restrict__ rrb,
    float* __restrict__ QW, float* __restrict__ QR,
    float* __restrict__ Kb, float* __restrict__ Vb, float* __restrict__ RK)
{
    int idx = blockIdx.x * 256 + threadIdx.x;
    int d = idx & 63;
    int i = (idx >> 6) & 1023;
    int z = idx >> 16;
    int b = z >> 4, h = z & 15;
    long long t = (long long)i * BSZ + b;
    int hd = h * 64 + d;
    float q  = wheads[t * 3072 + hd];
    float k  = wheads[t * 3072 + 1024 + hd];
    float v  = wheads[t * 3072 + 2048 + hd];
    float rk = rkraw[t * 1024 + hd];
    QW[idx] = __uint_as_float(f2tf32(q + rwb[hd]));
    QR[idx] = __uint_as_float(f2tf32(q + rrb[hd]));
    Kb[idx] = __uint_as_float(f2tf32(k));
    Vb[idx] = __uint_as_float(f2tf32(v));
    RK[idx] = __uint_as_float(f2tf32(rk));
}

// ---------------- semi-fused attention ----------------
#define QK_STR 68
#define VP_STR 132
#define A_KS  0
#define A_VS  8704
#define A_PS  17152
#define ATTN_SMEM ((17152 + 16896) * 4)

__global__ void __launch_bounds__(256) attn_kernel(
    const float* __restrict__ BD, const float* __restrict__ Kb,
    const float* __restrict__ Vb, const float* __restrict__ QW,
    float* __restrict__ AV)
{
    extern __shared__ float sm[];
    unsigned* Ps = (unsigned*)(sm + A_PS);
    unsigned sb = (unsigned)__cvta_generic_to_shared(sm);
    unsigned ks_a  = sb + A_KS * 4u;
    unsigned vs_a  = sb + A_VS * 4u;
    unsigned ps_a  = sb + A_PS * 4u;

    int it = (int)gridDim.x - 1 - blockIdx.x;
    int z = blockIdx.y;
    int b = z >> 4, h = z & 15;
    const float* Kz  = Kb + (long long)z * (QLEN * DH);
    const float* Vz  = Vb + (long long)z * (QLEN * DH);
    const float* QWz = QW + (long long)z * (QLEN * DH);
    const float* BDz = BD + (long long)z * (QLEN * QLEN);

    int tid = threadIdx.x;
    int wid = tid >> 5, lane = tid & 31;
    int r = lane >> 2, cc = lane & 3;
    int lrow = lane & 7, lsel = lane >> 3;
    int i0 = it << 7;
    int m0 = wid * 16;
    int rowA = m0 + r;
    int iA = i0 + rowA, iB = iA + 8;

    unsigned a_qk = (unsigned)(((m0 + (lsel & 1) * 8 + lrow) * QK_STR + (lsel >> 1) * 4) * 4);
    unsigned a_pv = ps_a + (unsigned)(((m0 + (lsel & 1) * 8 + lrow) * VP_STR + (lsel >> 1) * 4) * 4);
    unsigned bk_base[8], bv_base[4];
#pragma unroll
    for (int p = 0; p < 8; p++)
        bk_base[p] = ks_a + (unsigned)(((p * 16 + (lsel >> 1) * 8 + lrow) * QK_STR + (lsel & 1) * 4) * 4);
#pragma unroll
    for (int p = 0; p < 4; p++)
        bv_base[p] = vs_a + (unsigned)(((p * 16 + (lsel >> 1) * 8 + lrow) * VP_STR + (lsel & 1) * 4) * 4);

    float oacc[8][4];
#pragma unroll
    for (int ni = 0; ni < 8; ni++)
#pragma unroll
        for (int q = 0; q < 4; q++) oacc[ni][q] = 0.f;

    float mA = -1e30f, mB = -1e30f, lA = 0.f, lB = 0.f;

#pragma unroll
    for (int s = tid; s < 2048; s += 256) {
        int row = s >> 4, q = s & 15;
        CP16(ks_a + (unsigned)(row * QK_STR + q * 4) * 4u,
             Kz + (long long)row * DH + q * 4);
        CP16(ps_a + (unsigned)(row * QK_STR + q * 4) * 4u,
             QWz + (long long)(i0 + row) * DH + q * 4);
    }
    CP_COMMIT();
    CP_WAIT(0);
    __syncthreads();

    unsigned qwf[8][4];
#pragma unroll
    for (int ks = 0; ks < 8; ks++) {
        LDSM4(qwf[ks][0], qwf[ks][1], qwf[ks][2], qwf[ks][3],
              ps_a + a_qk + (unsigned)ks * 32u);
    }
    __syncthreads();

    const float SC2 = 0.18033688f;   // 0.125 * log2(e)

    for (int jt = 0; jt <= it; jt++) {
        int j0 = jt << 7;

#pragma unroll
        for (int s = tid; s < 8192; s += 256) {
            int d = s & 63, j = s >> 6;
            CP4(vs_a + (unsigned)(d * VP_STR + j) * 4u,
                Vz + (long long)(j0 + j) * DH + d);
        }
        CP_COMMIT();

        if (jt > 0) { CP_WAIT(1); }
        __syncthreads();

        float s_fr[16][4];
#pragma unroll
        for (int ni = 0; ni < 16; ni++)
#pragma unroll
            for (int q = 0; q < 4; q++) s_fr[ni][q] = 0.f;
#pragma unroll
        for (int ks = 0; ks < 8; ks++) {
            unsigned kbB = (unsigned)ks * 32u;
#pragma unroll
            for (int p = 0; p < 8; p++) {
                unsigned b0a, b1a, b0b, b1b;
                LDSM4(b0a, b1a, b0b, b1b, bk_base[p] + kbB);
                MMA_TF32(s_fr[2 * p][0], s_fr[2 * p][1], s_fr[2 * p][2], s_fr[2 * p][3],
                         qwf[ks][0], qwf[ks][1], qwf[ks][2], qwf[ks][3], b0a, b1a);
                MMA_TF32(s_fr[2 * p + 1][0], s_fr[2 * p + 1][1], s_fr[2 * p + 1][2], s_fr[2 * p + 1][3],
                         qwf[ks][0], qwf[ks][1], qwf[ks][2], qwf[ks][3], b0b, b1b);
            }
        }
        __syncthreads();

        if (jt < it) {
            int jn0 = (jt + 1) << 7;
#pragma unroll
            for (int s = tid; s < 2048; s += 256) {
                int row = s >> 4, q = s & 15;
                CP16(ks_a + (unsigned)(row * QK_STR + q * 4) * 4u,
                     Kz + (long long)(jn0 + row) * DH + q * 4);
            }
            CP_COMMIT();
            CP_WAIT(1);
        } else {
            CP_WAIT(0);
        }
        __syncthreads();

        {
            const float* bdA = BDz + (long long)iA * QLEN + (j0 - iA + QLEN - 1);
            const float* bdB = BDz + (long long)iB * QLEN + (j0 - iB + QLEN - 1);
            bool diag = (jt == it);
#pragma unroll
            for (int ni = 0; ni < 16; ni++) {
                int c0 = ni * 8 + cc * 2;
                float v0 = (s_fr[ni][0] + bdA[c0])     * SC2;
                float v1 = (s_fr[ni][1] + bdA[c0 + 1]) * SC2;
                float v2 = (s_fr[ni][2] + bdB[c0])     * SC2;
                float v3 = (s_fr[ni][3] + bdB[c0 + 1]) * SC2;
                if (diag) {
                    if (j0 + c0     > iA) v0 = -1e30f;
                    if (j0 + c0 + 1 > iA) v1 = -1e30f;
                    if (j0 + c0     > iB) v2 = -1e30f;
                    if (j0 + c0 + 1 > iB) v3 = -1e30f;
                }
                s_fr[ni][0] = v0; s_fr[ni][1] = v1;
                s_fr[ni][2] = v2; s_fr[ni][3] = v3;
            }
            float mxA = -1e30f, mxB = -1e30f;
#pragma unroll
            for (int ni = 0; ni < 16; ni++) {
                mxA = fmaxf(mxA, fmaxf(s_fr[ni][0], s_fr[ni][1]));
                mxB = fmaxf(mxB, fmaxf(s_fr[ni][2], s_fr[ni][3]));
            }
#pragma unroll
            for (int off = 1; off <= 2; off <<= 1) {
                mxA = fmaxf(mxA, __shfl_xor_sync(0xffffffffu, mxA, off));
                mxB = fmaxf(mxB, __shfl_xor_sync(0xffffffffu, mxB, off));
            }
            float mnA = fmaxf(mA, mxA), mnB = fmaxf(mB, mxB);
            float alA = ex2f(mA - mnA), alB = ex2f(mB - mnB);
            float psA = 0.f, psB = 0.f;
#pragma unroll
            for (int ni = 0; ni < 16; ni++) {
                float p0 = ex2f(s_fr[ni][0] - mnA);
                float p1 = ex2f(s_fr[ni][1] - mnA);
                float p2 = ex2f(s_fr[ni][2] - mnB);
                float p3 = ex2f(s_fr[ni][3] - mnB);
                psA += p0 + p1; psB += p2 + p3;
                int c0 = ni * 8 + cc * 2;
                *(uint2*)(Ps + rowA * VP_STR + c0) = make_uint2(f2tf32(p0), f2tf32(p1));
                *(uint2*)(Ps + (rowA + 8) * VP_STR + c0) = make_uint2(f2tf32(p2), f2tf32(p3));
            }
#pragma unroll
            for (int off = 1; off <= 2; off <<= 1) {
                psA += __shfl_xor_sync(0xffffffffu, psA, off);
                psB += __shfl_xor_sync(0xffffffffu, psB, off);
            }
            mA = mnA; mB = mnB;
            lA = lA * alA + psA; lB = lB * alB + psB;
#pragma unroll
            for (int ni = 0; ni < 8; ni++) {
                oacc[ni][0] *= alA; oacc[ni][1] *= alA;
                oacc[ni][2] *= alB; oacc[ni][3] *= alB;
            }
        }
        __syncwarp();

#pragma unroll
        for (int ks = 0; ks < 16; ks++) {
            unsigned kbB = (unsigned)ks * 32u;
            unsigned a0, a1, a2, a3;
            LDSM4(a0, a1, a2, a3, a_pv + kbB);
#pragma unroll
            for (int p = 0; p < 4; p++) {
                unsigned b0a, b1a, b0b, b1b;
                LDSM4(b0a, b1a, b0b, b1b, bv_base[p] + kbB);
                MMA_TF32(oacc[2 * p][0], oacc[2 * p][1], oacc[2 * p][2], oacc[2 * p][3],
                         a0, a1, a2, a3, b0a, b1a);
                MMA_TF32(oacc[2 * p + 1][0], oacc[2 * p + 1][1], oacc[2 * p + 1][2], oacc[2 * p + 1][3],
                         a0, a1, a2, a3, b0b, b1b);
            }
        }
        __syncthreads();
    }

    // normalize + store AV pre-rounded to tf32 (feeds O GEMM)
    float invA = 1.f / lA, invB = 1.f / lB;
    long long ta = (long long)iA * BSZ + b;
    long long tb = (long long)iB * BSZ + b;
#pragma unroll
    for (int ni = 0; ni < 8; ni++) {
        int d = ni * 8 + cc * 2;
        *(uint2*)(AV + ta * DM + h * 64 + d) =
            make_uint2(f2tf32(oacc[ni][0] * invA), f2tf32(oacc[ni][1] * invA));
        *(uint2*)(AV + tb * DM + h * 64 + d) =
            make_uint2(f2tf32(oacc[ni][2] * invB), f2tf32(oacc[ni][3] * invB));
    }
}

// ---------------- residual + layernorm ----------------
__global__ void __launch_bounds__(256) ln_kernel(
    const float* __restrict__ w, const float* __restrict__ ao,
    const float* __restrict__ g, const float* __restrict__ be,
    float* __restrict__ out)
{
    long long t = blockIdx.x;
    int tid = threadIdx.x;
    __shared__ float red[8];
    __shared__ float s_mu, s_rstd;

    float4 wx = *(const float4*)(w  + t * DM + tid * 4);
    float4 ax = *(const float4*)(ao + t * DM + tid * 4);
    float x0 = wx.x + ax.x, x1 = wx.y + ax.y, x2 = wx.z + ax.z, x3 = wx.w + ax.w;

    float s = x0 + x1 + x2 + x3;
#pragma unroll
    for (int off = 16; off >= 1; off >>= 1) s += __shfl_xor_sync(0xffffffffu, s, off);
    if ((tid & 31) == 0) red[tid >> 5] = s;
    __syncthreads();
    if (tid == 0) {
        float a = 0;
#pragma unroll
        for (int i2 = 0; i2 < 8; i2++) a += red[i2];
        s_mu = a * (1.f / DM);
    }
    __syncthreads();
    float mu = s_mu;
    float d0 = x0 - mu, d1 = x1 - mu, d2 = x2 - mu, d3 = x3 - mu;
    float v = d0 * d0 + d1 * d1 + d2 * d2 + d3 * d3;
#pragma unroll
    for (int off = 16; off >= 1; off >>= 1) v += __shfl_xor_sync(0xffffffffu, v, off);
    if ((tid & 31) == 0) red[tid >> 5] = v;
    __syncthreads();
    if (tid == 0) {
        float a = 0;
#pragma unroll
        for (int i2 = 0; i2 < 8; i2++) a += red[i2];
        s_rstd = rsqrtf(a * (1.f / DM) + 1e-5f);
    }
    __syncthreads();
    float rs = s_rstd;
    float4 gg = *(const float4*)(g  + tid * 4);
    float4 bb = *(const float4*)(be + tid * 4);
    float4 o = make_float4(d0 * rs * gg.x + bb.x, d1 * rs * gg.y + bb.y,
                           d2 * rs * gg.z + bb.z, d3 * rs * gg.w + bb.w);
    *(float4*)(out + t * DM + tid * 4) = o;
}

// ---------------- host launcher ----------------
extern "C" void kernel_launch(void* const* d_in, const int* in_sizes, int n_in,
                              void* d_out, int out_size)
{
    const float* w       = (const float*)d_in[0];
    const float* r       = (const float*)d_in[1];
    const float* rwb     = (const float*)d_in[2];
    const float* rrb     = (const float*)d_in[3];
    const float* qkv_w   = (const float*)d_in[4];
    const float* r_net_w = (const float*)d_in[5];
    const float* o_w     = (const float*)d_in[6];
    const float* gamma   = (const float*)d_in[7];
    const float* beta    = (const float*)d_in[8];
    float* out = (float*)d_out;

    float *wheads, *rkraw, *QW, *QR, *Kb, *Vb, *RK, *BD, *AV, *AO;
    float *wt, *rt, *qkvwt, *rnetwt, *owt;
    cudaGetSymbolAddress((void**)&wheads, g_wheads);
    cudaGetSymbolAddress((void**)&rkraw,  g_rkraw);
    cudaGetSymbolAddress((void**)&QW, g_QW);
    cudaGetSymbolAddress((void**)&QR, g_QR);
    cudaGetSymbolAddress((void**)&Kb, g_Kb);
    cudaGetSymbolAddress((void**)&Vb, g_Vb);
    cudaGetSymbolAddress((void**)&RK, g_RK);
    cudaGetSymbolAddress((void**)&BD, g_BD);
    cudaGetSymbolAddress((void**)&AV, g_AV);
    cudaGetSymbolAddress((void**)&AO, g_AO);
    cudaGetSymbolAddress((void**)&wt, g_wt);
    cudaGetSymbolAddress((void**)&rt, g_rt);
    cudaGetSymbolAddress((void**)&qkvwt, g_qkvwt);
    cudaGetSymbolAddress((void**)&rnetwt, g_rnetwt);
    cudaGetSymbolAddress((void**)&owt, g_owt);

    cudaFuncSetAttribute(gemm_mma_kernel, cudaFuncAttributeMaxDynamicSharedMemorySize, GEMM_SMEM);
    cudaFuncSetAttribute(attn_kernel, cudaFuncAttributeMaxDynamicSharedMemorySize, ATTN_SMEM);

    // 0) pre-round all operands to tf32 (one merged launch; 3.25Mi float4s)
    round_all_kernel<<<(3407872 + 255) / 256, 256>>>(w, r, qkv_w, r_net_w, o_w);

    // 1) w_heads = wt @ qkvwt^T   [4096 x 3072]
    gemm_mma_kernel<<<dim3(3072 / 128, T_TOK / 128, 1), 256, GEMM_SMEM>>>(
        wt, qkvwt, wheads, T_TOK, 3072, DM, 0, 0, 0, 0);
    // 2) r_head_k = rt @ rnetwt^T   [4096 x 1024]
    gemm_mma_kernel<<<dim3(DM / 128, T_TOK / 128, 1), 256, GEMM_SMEM>>>(
        rt, rnetwt, rkraw, T_TOK, DM, DM, 0, 0, 0, 0);
    // 3) split + biases (pre-round to tf32)
    split_kernel<<<(NZ * QLEN * DH) / 256, 256>>>(wheads, rkraw, rwb, rrb, QW, QR, Kb, Vb, RK);
    // 4) BD = (q+rrb) . rk   batched, band tiles
    gemm_mma_kernel<<<dim3(QLEN / 128, QLEN / 128, NZ), 256, GEMM_SMEM>>>(
        QR, RK, BD, QLEN, QLEN, DH,
        (long long)QLEN * DH, (long long)QLEN * DH, (long long)QLEN * QLEN, 2);
    // 5) semi-fused attention (writes AV pre-rounded)
    attn_kernel<<<dim3(QLEN / 128, NZ), 256, ATTN_SMEM>>>(BD, Kb, Vb, QW, AV);
    // 6) attn_out = AV @ owt^T
    gemm_mma_kernel<<<dim3(DM / 128, T_TOK / 128, 1), 256, GEMM_SMEM>>>(
        AV, owt, AO, T_TOK, DM, DM, 0, 0, 0, 0);
    // 7) residual + layernorm -> out (uses raw w)
    ln_kernel<<<T_TOK, 256>>>(w, AO, gamma, beta, out);
}

// round 17
// speedup vs baseline: 1.1175x; 1.0089x over previous
#include <cuda_runtime.h>
#include <cuda_bf16.h>

// ---------------- problem dims (fixed) ----------------
#define QLEN 1024
#define BSZ 4
#define DM 1024
#define NH 16
#define DH 64
#define T_TOK 4096
#define NZ 64

// ---------------- scratch (device globals; no cudaMalloc allowed) ----------------
__device__ float g_wheads[(size_t)T_TOK * 3 * DM];
__device__ float g_rkraw [(size_t)T_TOK * DM];
__device__ float g_QW[(size_t)NZ * QLEN * DH];
__device__ float g_QR[(size_t)NZ * QLEN * DH];
__device__ float g_Kb[(size_t)NZ * QLEN * DH];
__device__ float g_Vb[(size_t)NZ * QLEN * DH];
__device__ float g_RK[(size_t)NZ * QLEN * DH];
__device__ float g_BD[(size_t)NZ * QLEN * QLEN + 2048];
__device__ float g_AV[(size_t)T_TOK * DM];
__device__ float g_AO[(size_t)T_TOK * DM];
// tf32 pre-rounded operand copies
__device__ float g_wt  [(size_t)T_TOK * DM];
__device__ float g_rt  [(size_t)T_TOK * DM];
__device__ float g_qkvwt[(size_t)3 * DM * DM];
__device__ float g_rnetwt[(size_t)DM * DM];
__device__ float g_owt [(size_t)DM * DM];

__device__ __forceinline__ unsigned f2tf32(float x) {
    unsigned r;
    asm("cvt.rna.tf32.f32 %0, %1;" : "=r"(r) : "f"(x));
    return r;
}
__device__ __forceinline__ float ex2f(float x) {
    float y;
    asm("ex2.approx.f32 %0, %1;" : "=f"(y) : "f"(x));
    return y;
}

#define MMA_TF32(d0,d1,d2,d3, a0,a1,a2,a3, b0,b1) \
    asm volatile( \
        "mma.sync.aligned.m16n8k8.row.col.f32.tf32.tf32.f32 " \
        "{%0,%1,%2,%3}, {%4,%5,%6,%7}, {%8,%9}, {%0,%1,%2,%3};" \
        : "+f"(d0), "+f"(d1), "+f"(d2), "+f"(d3) \
        : "r"(a0), "r"(a1), "r"(a2), "r"(a3), "r"(b0), "r"(b1))

#define LDSM4(r0,r1,r2,r3, addr) \
    asm volatile("ldmatrix.sync.aligned.m8n8.x4.shared.b16 {%0,%1,%2,%3}, [%4];" \
        : "=r"(r0), "=r"(r1), "=r"(r2), "=r"(r3) : "r"(addr))

#define CP16(dst_u32, src_ptr) \
    asm volatile("cp.async.cg.shared.global [%0], [%1], 16;" \
                 :: "r"(dst_u32), "l"(src_ptr))
#define CP4(dst_u32, src_ptr) \
    asm volatile("cp.async.ca.shared.global [%0], [%1], 4;" \
                 :: "r"(dst_u32), "l"(src_ptr))
#define CP_COMMIT() asm volatile("cp.async.commit_group;")
#define CP_WAIT(n)  asm volatile("cp.async.wait_group %0;" :: "n"(n))

// ---------------- merged RNA tf32 round of all 5 operand arrays ----------------
__global__ void __launch_bounds__(256) round_all_kernel(
    const float* __restrict__ w, const float* __restrict__ r,
    const float* __restrict__ qkvw, const float* __restrict__ rnetw,
    const float* __restrict__ ow)
{
    int i = blockIdx.x * 256 + threadIdx.x;   // 0 .. 3,407,871
    const float* src; float* dst; int off;
    if (i < 1048576)        { src = w;     dst = g_wt;     off = i; }
    else if (i < 2097152)   { src = r;     dst = g_rt;     off = i - 1048576; }
    else if (i < 2883584)   { src = qkvw;  dst = g_qkvwt;  off = i - 2097152; }
    else if (i < 3145728)   { src = rnetw; dst = g_rnetwt; off = i - 2883584; }
    else                    { src = ow;    dst = g_owt;    off = i - 3145728; }
    float4 v = *(const float4*)(src + (size_t)off * 4);
    uint4 u = make_uint4(f2tf32(v.x), f2tf32(v.y), f2tf32(v.z), f2tf32(v.w));
    *(uint4*)(dst + (size_t)off * 4) = u;
}

// ---------------- mma.sync tf32 GEMM, 3-stage cp.async pipeline ----------------
#define SSTRIDE 36
#define STAGE_B 36864
#define GEMM_SMEM (3 * STAGE_B)

__global__ void __launch_bounds__(256, 2) gemm_mma_kernel(
    const float* __restrict__ A, const float* __restrict__ B, float* __restrict__ C,
    int M, int N, int K, long long sA, long long sB, long long sC, int tri)
{
    int bx = blockIdx.x, by = blockIdx.y, z = blockIdx.z;
    if (tri == 2 && (bx + by) < (int)gridDim.x - 1) return;

    extern __shared__ float smp[];
    unsigned sbase = (unsigned)__cvta_generic_to_shared(smp);

    int tid = threadIdx.x;
    int wid = tid >> 5, lane = tid & 31;
    int warp_m = wid & 3, warp_n = wid >> 2;
    int r = lane >> 2, cc = lane & 3;
    int lrow = lane & 7, lsel = lane >> 3;

    unsigned a_base[2], b_base[4];
#pragma unroll
    for (int mi = 0; mi < 2; mi++)
        a_base[mi] = (unsigned)(((warp_m * 32 + mi * 16 + (lsel & 1) * 8 + lrow) * SSTRIDE
                                 + (lsel >> 1) * 4) * 4);
#pragma unroll
    for (int p = 0; p < 4; p++)
        b_base[p] = (unsigned)(((warp_n * 64 + p * 16 + (lsel >> 1) * 8 + lrow) * SSTRIDE
                                + (lsel & 1) * 4) * 4) + 18432u;

    const float* Ab = A + (long long)z * sA + (long long)(by * 128) * K;
    const float* Bb = B + (long long)z * sB + (long long)(bx * 128) * K;

    float acc[2][8][4];
#pragma unroll
    for (int mi = 0; mi < 2; mi++)
#pragma unroll
        for (int ni = 0; ni < 8; ni++)
#pragma unroll
            for (int q = 0; q < 4; q++) acc[mi][ni][q] = 0.f;

    int nch = K >> 5;

    for (int s0 = 0; s0 < 2 && s0 < nch; s0++) {
        unsigned st = sbase + (unsigned)(s0 * STAGE_B);
        int k0 = s0 << 5;
#pragma unroll
        for (int s = tid; s < 1024; s += 256) {
            int row = s >> 3, q = s & 7;
            unsigned off = (unsigned)(row * SSTRIDE + q * 4) * 4u;
            CP16(st + off, Ab + (long long)row * K + k0 + q * 4);
            CP16(st + 18432u + off, Bb + (long long)row * K + k0 + q * 4);
        }
        CP_COMMIT();
    }

    for (int c = 0; c < nch; c++) {
        if (c + 1 < nch) { CP_WAIT(1); } else { CP_WAIT(0); }
        __syncthreads();

        if (c + 2 < nch) {
            int k0 = (c + 2) << 5;
            unsigned st = sbase + (unsigned)(((c + 2) % 3) * STAGE_B);
#pragma unroll
            for (int s = tid; s < 1024; s += 256) {
                int row = s >> 3, q = s & 7;
                unsigned off = (unsigned)(row * SSTRIDE + q * 4) * 4u;
                CP16(st + off, Ab + (long long)row * K + k0 + q * 4);
                CP16(st + 18432u + off, Bb + (long long)row * K + k0 + q * 4);
            }
            CP_COMMIT();
        }

        unsigned stg = sbase + (unsigned)((c % 3) * STAGE_B);
#pragma unroll
        for (int ks = 0; ks < 4; ks++) {
            unsigned kbB = (unsigned)ks * 32u;
            unsigned a[2][4], bq[4][4];
            LDSM4(a[0][0], a[0][1], a[0][2], a[0][3], stg + a_base[0] + kbB);
            LDSM4(a[1][0], a[1][1], a[1][2], a[1][3], stg + a_base[1] + kbB);
#pragma unroll
            for (int p = 0; p < 4; p++)
                LDSM4(bq[p][0], bq[p][1], bq[p][2], bq[p][3], stg + b_base[p] + kbB);
#pragma unroll
            for (int ni = 0; ni < 8; ni++) {
                unsigned b0 = bq[ni >> 1][(ni & 1) * 2];
                unsigned b1 = bq[ni >> 1][(ni & 1) * 2 + 1];
#pragma unroll
                for (int mi = 0; mi < 2; mi++) {
                    MMA_TF32(acc[mi][ni][0], acc[mi][ni][1], acc[mi][ni][2], acc[mi][ni][3],
                             a[mi][0], a[mi][1], a[mi][2], a[mi][3], b0, b1);
                }
            }
        }
    }

    float* Cb = C + (long long)z * sC;
#pragma unroll
    for (int mi = 0; mi < 2; mi++) {
        int m = by * 128 + warp_m * 32 + mi * 16 + r;
#pragma unroll
        for (int ni = 0; ni < 8; ni++) {
            int n = bx * 128 + warp_n * 64 + ni * 8 + cc * 2;
            *(float2*)(Cb + (long long)m * N + n) =
                make_float2(acc[mi][ni][0], acc[mi][ni][1]);
            *(float2*)(Cb + (long long)(m + 8) * N + n) =
                make_float2(acc[mi][ni][2], acc[mi][ni][3]);
        }
    }
}

// ---------------- split heads + biases (pre-rounded to tf32 via RNA) ----------------
__global__ void __launch_bounds__(256) split_kernel(
    const float* __restrict__ wheads, const float* __restrict__ rkraw,
    const float* __restrict__ rwb, const float* __restrict__ rrb,
    float* __restrict__ QW, float* __restrict__ QR,
    float* __restrict__ Kb, float* __restrict__ Vb, float* __restrict__ RK)
{
    int idx = blockIdx.x * 256 + threadIdx.x;
    int d = idx & 63;
    int i = (idx >> 6) & 1023;
    int z = idx >> 16;
    int b = z >> 4, h = z & 15;
    long long t = (long long)i * BSZ + b;
    int hd = h * 64 + d;
    float q  = wheads[t * 3072 + hd];
    float k  = wheads[t * 3072 + 1024 + hd];
    float v  = wheads[t * 3072 + 2048 + hd];
    float rk = rkraw[t * 1024 + hd];
    QW[idx] = __uint_as_float(f2tf32(q + rwb[hd]));
    QR[idx] = __uint_as_float(f2tf32(q + rrb[hd]));
    Kb[idx] = __uint_as_float(f2tf32(k));
    Vb[idx] = __uint_as_float(f2tf32(v));
    RK[idx] = __uint_as_float(f2tf32(rk));
}

// ---------------- semi-fused attention, 64-wide j-subtiles, 2 CTAs/SM ----------------
// smem (floats): Ks [64][68] @0 | Vs [64][68] @4352 | Ps [128][68] @8704 | QWs [128][68] @17408
// Total 26112 floats = 104,448 B -> 2 CTAs/SM.
#define QK_STR 68
#define A_KS  0
#define A_VS  4352
#define A_PS  8704
#define A_QWS 17408
#define ATTN_SMEM (26112 * 4)

__global__ void __launch_bounds__(256, 2) attn_kernel(
    const float* __restrict__ BD, const float* __restrict__ Kb,
    const float* __restrict__ Vb, const float* __restrict__ QW,
    float* __restrict__ AV)
{
    extern __shared__ float sm[];
    unsigned* Ps = (unsigned*)(sm + A_PS);
    unsigned sb = (unsigned)__cvta_generic_to_shared(sm);
    unsigned ks_a  = sb + A_KS * 4u;
    unsigned vs_a  = sb + A_VS * 4u;
    unsigned ps_a  = sb + A_PS * 4u;
    unsigned qws_a = sb + A_QWS * 4u;

    int it = (int)gridDim.x - 1 - blockIdx.x;     // heavy tiles first
    int z = blockIdx.y;
    int b = z >> 4, h = z & 15;
    const float* Kz  = Kb + (long long)z * (QLEN * DH);
    const float* Vz  = Vb + (long long)z * (QLEN * DH);
    const float* QWz = QW + (long long)z * (QLEN * DH);
    const float* BDz = BD + (long long)z * (QLEN * QLEN);

    int tid = threadIdx.x;
    int wid = tid >> 5, lane = tid & 31;
    int r = lane >> 2, cc = lane & 3;
    int lrow = lane & 7, lsel = lane >> 3;
    int i0 = it << 7;
    int m0 = wid * 16;
    int rowA = m0 + r;
    int iA = i0 + rowA, iB = iA + 8;

    // ldmatrix lane-address bases (stride QK_STR everywhere)
    unsigned a_qw = qws_a + (unsigned)(((m0 + (lsel & 1) * 8 + lrow) * QK_STR + (lsel >> 1) * 4) * 4);
    unsigned a_pv = ps_a  + (unsigned)(((m0 + (lsel & 1) * 8 + lrow) * QK_STR + (lsel >> 1) * 4) * 4);
    unsigned bk_base[4], bv_base[4];
#pragma unroll
    for (int p = 0; p < 4; p++) {
        unsigned ro = (unsigned)(((p * 16 + (lsel >> 1) * 8 + lrow) * QK_STR + (lsel & 1) * 4) * 4);
        bk_base[p] = ks_a + ro;
        bv_base[p] = vs_a + ro;
    }

    float oacc[8][4];
#pragma unroll
    for (int ni = 0; ni < 8; ni++)
#pragma unroll
        for (int q = 0; q < 4; q++) oacc[ni][q] = 0.f;

    float mA = -1e30f, mB = -1e30f, lA = 0.f, lB = 0.f;

    // ---- prologue: QW (persistent) + K(0) ----
#pragma unroll
    for (int s = tid; s < 2048; s += 256) {
        int row = s >> 4, q = s & 15;
        CP16(qws_a + (unsigned)(row * QK_STR + q * 4) * 4u,
             QWz + (long long)(i0 + row) * DH + q * 4);
    }
#pragma unroll
    for (int s = tid; s < 1024; s += 256) {
        int row = s >> 4, q = s & 15;
        CP16(ks_a + (unsigned)(row * QK_STR + q * 4) * 4u,
             Kz + (long long)row * DH + q * 4);
    }
    CP_COMMIT();
    CP_WAIT(0);
    __syncthreads();

    const float SC2 = 0.18033688f;   // 0.125 * log2(e)
    int nj = 2 * (it + 1);           // number of 64-wide j subtiles

    for (int js = 0; js < nj; js++) {
        int j0 = js << 6;

        // ---- AC MMA: S (QWs x Ks) -> 8 ni fragments (64 cols) ----
        float s_fr[8][4];
#pragma unroll
        for (int ni = 0; ni < 8; ni++)
#pragma unroll
            for (int q = 0; q < 4; q++) s_fr[ni][q] = 0.f;
#pragma unroll
        for (int ks = 0; ks < 8; ks++) {
            unsigned kbB = (unsigned)ks * 32u;
            unsigned a0, a1, a2, a3;
            LDSM4(a0, a1, a2, a3, a_qw + kbB);
#pragma unroll
            for (int p = 0; p < 4; p++) {
                unsigned b0a, b1a, b0b, b1b;
                LDSM4(b0a, b1a, b0b, b1b, bk_base[p] + kbB);
                MMA_TF32(s_fr[2 * p][0], s_fr[2 * p][1], s_fr[2 * p][2], s_fr[2 * p][3],
                         a0, a1, a2, a3, b0a, b1a);
                MMA_TF32(s_fr[2 * p + 1][0], s_fr[2 * p + 1][1], s_fr[2 * p + 1][2], s_fr[2 * p + 1][3],
                         a0, a1, a2, a3, b0b, b1b);
            }
        }
        __syncthreads();   // Ks consumed; PV(js-1) complete (all warps past it)

        // ---- issue K(js+1) + V(js) (one group) ----
        if (js + 1 < nj) {
            int jn0 = (js + 1) << 6;
#pragma unroll
            for (int s = tid; s < 1024; s += 256) {
                int row = s >> 4, q = s & 15;
                CP16(ks_a + (unsigned)(row * QK_STR + q * 4) * 4u,
                     Kz + (long long)(jn0 + row) * DH + q * 4);
            }
        }
#pragma unroll
        for (int s = tid; s < 4096; s += 256) {
            int d = s & 63, j = s >> 6;
            CP4(vs_a + (unsigned)(d * QK_STR + j) * 4u,
                Vz + (long long)(j0 + j) * DH + d);
        }
        CP_COMMIT();

        // ---- softmax on fragments (BD gather from global, ex2 domain) ----
        {
            const float* bdA = BDz + (long long)iA * QLEN + (j0 - iA + QLEN - 1);
            const float* bdB = BDz + (long long)iB * QLEN + (j0 - iB + QLEN - 1);
            bool diag = (js >= nj - 2);
#pragma unroll
            for (int ni = 0; ni < 8; ni++) {
                int c0 = ni * 8 + cc * 2;
                float v0 = (s_fr[ni][0] + bdA[c0])     * SC2;
                float v1 = (s_fr[ni][1] + bdA[c0 + 1]) * SC2;
                float v2 = (s_fr[ni][2] + bdB[c0])     * SC2;
                float v3 = (s_fr[ni][3] + bdB[c0 + 1]) * SC2;
                if (diag) {
                    if (j0 + c0     > iA) v0 = -1e30f;
                    if (j0 + c0 + 1 > iA) v1 = -1e30f;
                    if (j0 + c0     > iB) v2 = -1e30f;
                    if (j0 + c0 + 1 > iB) v3 = -1e30f;
                }
                s_fr[ni][0] = v0; s_fr[ni][1] = v1;
                s_fr[ni][2] = v2; s_fr[ni][3] = v3;
            }
            float mxA = -1e30f, mxB = -1e30f;
#pragma unroll
            for (int ni = 0; ni < 8; ni++) {
                mxA = fmaxf(mxA, fmaxf(s_fr[ni][0], s_fr[ni][1]));
                mxB = fmaxf(mxB, fmaxf(s_fr[ni][2], s_fr[ni][3]));
            }
#pragma unroll
            for (int off = 1; off <= 2; off <<= 1) {
                mxA = fmaxf(mxA, __shfl_xor_sync(0xffffffffu, mxA, off));
                mxB = fmaxf(mxB, __shfl_xor_sync(0xffffffffu, mxB, off));
            }
            float mnA = fmaxf(mA, mxA), mnB = fmaxf(mB, mxB);
            float alA = ex2f(mA - mnA), alB = ex2f(mB - mnB);
            float psA = 0.f, psB = 0.f;
#pragma unroll
            for (int ni = 0; ni < 8; ni++) {
                float p0 = ex2f(s_fr[ni][0] - mnA);
                float p1 = ex2f(s_fr[ni][1] - mnA);
                float p2 = ex2f(s_fr[ni][2] - mnB);
                float p3 = ex2f(s_fr[ni][3] - mnB);
                psA += p0 + p1; psB += p2 + p3;
                int c0 = ni * 8 + cc * 2;
                *(uint2*)(Ps + rowA * QK_STR + c0) = make_uint2(f2tf32(p0), f2tf32(p1));
                *(uint2*)(Ps + (rowA + 8) * QK_STR + c0) = make_uint2(f2tf32(p2), f2tf32(p3));
            }
#pragma unroll
            for (int off = 1; off <= 2; off <<= 1) {
                psA += __shfl_xor_sync(0xffffffffu, psA, off);
                psB += __shfl_xor_sync(0xffffffffu, psB, off);
            }
            mA = mnA; mB = mnB;
            lA = lA * alA + psA; lB = lB * alB + psB;
#pragma unroll
            for (int ni = 0; ni < 8; ni++) {
                oacc[ni][0] *= alA; oacc[ni][1] *= alA;
                oacc[ni][2] *= alB; oacc[ni][3] *= alB;
            }
        }
        __syncwarp();   // P rows warp-private: order STS -> LDSM within warp

        // ---- V (and next K) landed; PV MMA ----
        CP_WAIT(0);
        __syncthreads();
#pragma unroll
        for (int ks = 0; ks < 8; ks++) {
            unsigned kbB = (unsigned)ks * 32u;
            unsigned a0, a1, a2, a3;
            LDSM4(a0, a1, a2, a3, a_pv + kbB);
#pragma unroll
            for (int p = 0; p < 4; p++) {
                unsigned b0a, b1a, b0b, b1b;
                LDSM4(b0a, b1a, b0b, b1b, bv_base[p] + kbB);
                MMA_TF32(oacc[2 * p][0], oacc[2 * p][1], oacc[2 * p][2], oacc[2 * p][3],
                         a0, a1, a2, a3, b0a, b1a);
                MMA_TF32(oacc[2 * p + 1][0], oacc[2 * p + 1][1], oacc[2 * p + 1][2], oacc[2 * p + 1][3],
                         a0, a1, a2, a3, b0b, b1b);
            }
        }
        // no trailing sync: next iteration's post-AC barrier protects Vs/Ps
    }

    // normalize + store AV pre-rounded to tf32 (feeds O GEMM)
    float invA = 1.f / lA, invB = 1.f / lB;
    long long ta = (long long)iA * BSZ + b;
    long long tb = (long long)iB * BSZ + b;
#pragma unroll
    for (int ni = 0; ni < 8; ni++) {
        int d = ni * 8 + cc * 2;
        *(uint2*)(AV + ta * DM + h * 64 + d) =
            make_uint2(f2tf32(oacc[ni][0] * invA), f2tf32(oacc[ni][1] * invA));
        *(uint2*)(AV + tb * DM + h * 64 + d) =
            make_uint2(f2tf32(oacc[ni][2] * invB), f2tf32(oacc[ni][3] * invB));
    }
}

// ---------------- residual + layernorm ----------------
__global__ void __launch_bounds__(256) ln_kernel(
    const float* __restrict__ w, const float* __restrict__ ao,
    const float* __restrict__ g, const float* __restrict__ be,
    float* __restrict__ out)
{
    long long t = blockIdx.x;
    int tid = threadIdx.x;
    __shared__ float red[8];
    __shared__ float s_mu, s_rstd;

    float4 wx = *(const float4*)(w  + t * DM + tid * 4);
    float4 ax = *(const float4*)(ao + t * DM + tid * 4);
    float x0 = wx.x + ax.x, x1 = wx.y + ax.y, x2 = wx.z + ax.z, x3 = wx.w + ax.w;

    float s = x0 + x1 + x2 + x3;
#pragma unroll
    for (int off = 16; off >= 1; off >>= 1) s += __shfl_xor_sync(0xffffffffu, s, off);
    if ((tid & 31) == 0) red[tid >> 5] = s;
    __syncthreads();
    if (tid == 0) {
        float a = 0;
#pragma unroll
        for (int i2 = 0; i2 < 8; i2++) a += red[i2];
        s_mu = a * (1.f / DM);
    }
    __syncthreads();
    float mu = s_mu;
    float d0 = x0 - mu, d1 = x1 - mu, d2 = x2 - mu, d3 = x3 - mu;
    float v = d0 * d0 + d1 * d1 + d2 * d2 + d3 * d3;
#pragma unroll
    for (int off = 16; off >= 1; off >>= 1) v += __shfl_xor_sync(0xffffffffu, v, off);
    if ((tid & 31) == 0) red[tid >> 5] = v;
    __syncthreads();
    if (tid == 0) {
        float a = 0;
#pragma unroll
        for (int i2 = 0; i2 < 8; i2++) a += red[i2];
        s_rstd = rsqrtf(a * (1.f / DM) + 1e-5f);
    }
    __syncthreads();
    float rs = s_rstd;
    float4 gg = *(const float4*)(g  + tid * 4);
    float4 bb = *(const float4*)(be + tid * 4);
    float4 o = make_float4(d0 * rs * gg.x + bb.x, d1 * rs * gg.y + bb.y,
                           d2 * rs * gg.z + bb.z, d3 * rs * gg.w + bb.w);
    *(float4*)(out + t * DM + tid * 4) = o;
}

// ---------------- host launcher ----------------
extern "C" void kernel_launch(void* const* d_in, const int* in_sizes, int n_in,
                              void* d_out, int out_size)
{
    const float* w       = (const float*)d_in[0];
    const float* r       = (const float*)d_in[1];
    const float* rwb     = (const float*)d_in[2];
    const float* rrb     = (const float*)d_in[3];
    const float* qkv_w   = (const float*)d_in[4];
    const float* r_net_w = (const float*)d_in[5];
    const float* o_w     = (const float*)d_in[6];
    const float* gamma   = (const float*)d_in[7];
    const float* beta    = (const float*)d_in[8];
    float* out = (float*)d_out;

    float *wheads, *rkraw, *QW, *QR, *Kb, *Vb, *RK, *BD, *AV, *AO;
    float *wt, *rt, *qkvwt, *rnetwt, *owt;
    cudaGetSymbolAddress((void**)&wheads, g_wheads);
    cudaGetSymbolAddress((void**)&rkraw,  g_rkraw);
    cudaGetSymbolAddress((void**)&QW, g_QW);
    cudaGetSymbolAddress((void**)&QR, g_QR);
    cudaGetSymbolAddress((void**)&Kb, g_Kb);
    cudaGetSymbolAddress((void**)&Vb, g_Vb);
    cudaGetSymbolAddress((void**)&RK, g_RK);
    cudaGetSymbolAddress((void**)&BD, g_BD);
    cudaGetSymbolAddress((void**)&AV, g_AV);
    cudaGetSymbolAddress((void**)&AO, g_AO);
    cudaGetSymbolAddress((void**)&wt, g_wt);
    cudaGetSymbolAddress((void**)&rt, g_rt);
    cudaGetSymbolAddress((void**)&qkvwt, g_qkvwt);
    cudaGetSymbolAddress((void**)&rnetwt, g_rnetwt);
    cudaGetSymbolAddress((void**)&owt, g_owt);

    cudaFuncSetAttribute(gemm_mma_kernel, cudaFuncAttributeMaxDynamicSharedMemorySize, GEMM_SMEM);
    cudaFuncSetAttribute(attn_kernel, cudaFuncAttributeMaxDynamicSharedMemorySize, ATTN_SMEM);

    // 0) pre-round all operands to tf32 (one merged launch)
    round_all_kernel<<<(3407872 + 255) / 256, 256>>>(w, r, qkv_w, r_net_w, o_w);

    // 1) w_heads = wt @ qkvwt^T   [4096 x 3072]
    gemm_mma_kernel<<<dim3(3072 / 128, T_TOK / 128, 1), 256, GEMM_SMEM>>>(
        wt, qkvwt, wheads, T_TOK, 3072, DM, 0, 0, 0, 0);
    // 2) r_head_k = rt @ rnetwt^T   [4096 x 1024]
    gemm_mma_kernel<<<dim3(DM / 128, T_TOK / 128, 1), 256, GEMM_SMEM>>>(
        rt, rnetwt, rkraw, T_TOK, DM, DM, 0, 0, 0, 0);
    // 3) split + biases (pre-round to tf32)
    split_kernel<<<(NZ * QLEN * DH) / 256, 256>>>(wheads, rkraw, rwb, rrb, QW, QR, Kb, Vb, RK);
    // 4) BD = (q+rrb) . rk   batched, band tiles
    gemm_mma_kernel<<<dim3(QLEN / 128, QLEN / 128, NZ), 256, GEMM_SMEM>>>(
        QR, RK, BD, QLEN, QLEN, DH,
        (long long)QLEN * DH, (long long)QLEN * DH, (long long)QLEN * QLEN, 2);
    // 5) semi-fused attention (64-wide subtiles, 2 CTAs/SM)
    attn_kernel<<<dim3(QLEN / 128, NZ), 256, ATTN_SMEM>>>(BD, Kb, Vb, QW, AV);
    // 6) attn_out = AV @ owt^T
    gemm_mma_kernel<<<dim3(DM / 128, T_TOK / 128, 1), 256, GEMM_SMEM>>>(
        AV, owt, AO, T_TOK, DM, DM, 0, 0, 0, 0);
    // 7) residual + layernorm -> out (uses raw w)
    ln_kernel<<<T_TOK, 256>>>(w, AO, gamma, beta, out);
}